// round 11
// baseline (speedup 1.0000x reference)
#include <cuda_runtime.h>

#define DIMC 1024
#define NHEAD 16
#define HDIM 64
#define BATCH 4
#define SEQ 2048
#define MTOT (BATCH*SEQ)
#define NQKV (3*DIMC)

// All intermediates hold TF32 bit patterns
__device__ unsigned g_xtf [(size_t)MTOT*DIMC];
__device__ unsigned g_wqkv[(size_t)DIMC*NQKV];
__device__ unsigned g_wprj[(size_t)DIMC*DIMC];
__device__ unsigned g_qkv [(size_t)3*BATCH*NHEAD*SEQ*HDIM];  // [3][B][H][S][D]
__device__ unsigned g_attn[(size_t)MTOT*DIMC];               // [B*S][C] tf32

__device__ __forceinline__ unsigned f2tf(float x){
    unsigned r; asm("cvt.rna.tf32.f32 %0,%1;" : "=r"(r) : "f"(x)); return r;
}

__device__ __forceinline__ void mma8(float* c, const unsigned* a, const unsigned* b){
    asm volatile(
      "mma.sync.aligned.m16n8k8.row.col.f32.tf32.tf32.f32 "
      "{%0,%1,%2,%3},{%4,%5,%6,%7},{%8,%9},{%0,%1,%2,%3};\n"
      : "+f"(c[0]),"+f"(c[1]),"+f"(c[2]),"+f"(c[3])
      : "r"(a[0]),"r"(a[1]),"r"(a[2]),"r"(a[3]),"r"(b[0]),"r"(b[1]));
}

__global__ __launch_bounds__(256)
void cvt_tf32(const float4* __restrict__ src, uint4* __restrict__ dst, int n4)
{
    int i = blockIdx.x*256 + threadIdx.x;
    if(i < n4){
        float4 v = src[i];
        dst[i] = make_uint4(f2tf(v.x), f2tf(v.y), f2tf(v.z), f2tf(v.w));
    }
}

// ---------------------------------------------------------------------------
// Tensor-core GEMM: 64x64 warp tiles, 128 threads, 128x128x16 tiles.
// A smem XOR-swizzled: phys m' = m ^ ((k&12)<<1)  -> conflict-free A stores
// (was 4-way since R2) AND conflict-free fragment loads.
// ---------------------------------------------------------------------------
#define ASTR 136
#define BSTR 136

template<int N, bool SCATTER>
__global__ __launch_bounds__(128)
void gemm_mma(const unsigned* __restrict__ A, const unsigned* __restrict__ B,
              const float* __restrict__ bias, float* __restrict__ out)
{
    __shared__ __align__(16) unsigned As[2][16*ASTR];
    __shared__ __align__(16) unsigned Bs[2][16*BSTR];
    const int tid=threadIdx.x, lane=tid&31, warp=tid>>5;
    const int g=lane>>2, tg=lane&3;
    const int mbase=(warp&1)*64, nbase=(warp>>1)*64;
    const int bm=blockIdx.y*128, bn=blockIdx.x*128;
    const unsigned* Ab = (SCATTER ? A : (const unsigned*)g_attn) + (size_t)bm*DIMC;
    const unsigned* Bb = B + bn;

    uint4 ar[4], br[4];
    float acc[4][8][4];
    #pragma unroll
    for(int i=0;i<4;i++)
      #pragma unroll
      for(int j=0;j<8;j++)
        #pragma unroll
        for(int k=0;k<4;k++) acc[i][j][k]=0.f;

    const int NT = DIMC/16;

    #pragma unroll
    for(int i=0;i<4;i++){
        int idx=tid+(i<<7);
        ar[i]=*(const uint4*)(Ab + (size_t)(idx>>2)*DIMC + ((idx&3)<<2));
        br[i]=*(const uint4*)(Bb + (size_t)(idx>>5)*N + ((idx&31)<<2));
    }
    #pragma unroll
    for(int i=0;i<4;i++){
        int idx=tid+(i<<7);
        int r=idx>>2, kc=(idx&3)<<2;
        int rs = r ^ (kc<<1);            // swizzle: kc==k&12 for j in 0..3
        As[0][(kc+0)*ASTR+rs]=ar[i].x;
        As[0][(kc+1)*ASTR+rs]=ar[i].y;
        As[0][(kc+2)*ASTR+rs]=ar[i].z;
        As[0][(kc+3)*ASTR+rs]=ar[i].w;
        int rb=idx>>5, cb=(idx&31)<<2;
        *(uint4*)&Bs[0][rb*BSTR+cb]=br[i];
    }
    __syncthreads();

    for(int kt=0;kt<NT;kt++){
        const int buf=kt&1;
        if(kt<NT-1){
            #pragma unroll
            for(int i=0;i<4;i++){
                int idx=tid+(i<<7);
                ar[i]=*(const uint4*)(Ab + (size_t)(idx>>2)*DIMC + (kt+1)*16 + ((idx&3)<<2));
                br[i]=*(const uint4*)(Bb + (size_t)((kt+1)*16+(idx>>5))*N + ((idx&31)<<2));
            }
        }
        #pragma unroll
        for(int ks=0;ks<2;ks++){
            const int k0=ks*8;
            const int sw01 = (k0&12)<<1;         // k in [k0, k0+4)
            const int sw23 = ((k0+4)&12)<<1;     // k in [k0+4, k0+8)
            unsigned af[4][4], bf[8][2];
            #pragma unroll
            for(int mi=0;mi<4;mi++){
                const int m0=mbase+mi*16;
                af[mi][0]=As[buf][(k0+tg  )*ASTR+((m0+g  )^sw01)];
                af[mi][1]=As[buf][(k0+tg  )*ASTR+((m0+g+8)^sw01)];
                af[mi][2]=As[buf][(k0+tg+4)*ASTR+((m0+g  )^sw23)];
                af[mi][3]=As[buf][(k0+tg+4)*ASTR+((m0+g+8)^sw23)];
            }
            #pragma unroll
            for(int ni=0;ni<8;ni++){
                const int n0=nbase+ni*8;
                bf[ni][0]=Bs[buf][(k0+tg)*BSTR+n0+g];
                bf[ni][1]=Bs[buf][(k0+tg+4)*BSTR+n0+g];
            }
            #pragma unroll
            for(int mi=0;mi<4;mi++)
                #pragma unroll
                for(int ni=0;ni<8;ni++)
                    mma8(acc[mi][ni],af[mi],bf[ni]);
        }
        if(kt<NT-1){
            #pragma unroll
            for(int i=0;i<4;i++){
                int idx=tid+(i<<7);
                int r=idx>>2, kc=(idx&3)<<2;
                int rs = r ^ (kc<<1);
                As[buf^1][(kc+0)*ASTR+rs]=ar[i].x;
                As[buf^1][(kc+1)*ASTR+rs]=ar[i].y;
                As[buf^1][(kc+2)*ASTR+rs]=ar[i].z;
                As[buf^1][(kc+3)*ASTR+rs]=ar[i].w;
                int rb=idx>>5, cb=(idx&31)<<2;
                *(uint4*)&Bs[buf^1][rb*BSTR+cb]=br[i];
            }
        }
        __syncthreads();
    }

    #pragma unroll
    for(int mi=0;mi<4;mi++){
        #pragma unroll
        for(int ni=0;ni<8;ni++){
            #pragma unroll
            for(int e=0;e<4;e++){
                const int r = bm + mbase + mi*16 + g + ((e>=2)?8:0);
                const int c = bn + nbase + ni*8 + 2*tg + (e&1);
                const float v = acc[mi][ni][e] + bias[c];
                if(SCATTER){
                    const int b=r>>11, s=r&2047;
                    const int t=c>>10, h=(c>>6)&15, d=c&63;
                    g_qkv[((((size_t)t*BATCH+b)*NHEAD+h)*SEQ+s)*HDIM+d]=f2tf(v);
                } else {
                    out[(size_t)r*N+c]=v;
                }
            }
        }
    }
}

// ---------------------------------------------------------------------------
// Flash attention: 128 threads, 4 warps x 32 q-rows, q-tile 128, k-tile 64.
// P fragment buffer uses lane-transposed layout sigma(l)=(l&3)*8+(l>>2):
// stores spread to 16 even bank-starts (2 wf) instead of 8 (4 wf).
// ---------------------------------------------------------------------------
#define QKOFF ((size_t)BATCH*NHEAD*SEQ*HDIM)
#define FSTR 68
#define FLASH_SMEM ((128*FSTR + 2*64*FSTR + 4*2048)*4)   /* 102400 B */

__global__ __launch_bounds__(128)
void flash_mma()
{
    extern __shared__ __align__(16) unsigned sm[];
    unsigned* Qs=sm;
    unsigned* Ks=Qs+128*FSTR;
    unsigned* Vs=Ks+64*FSTR;
    unsigned* Ps=Vs+64*FSTR;
    const int tid=threadIdx.x, lane=tid&31, warp=tid>>5;
    const int g=lane>>2, tg=lane&3;
    const int qb=warp*32;
    const int b=blockIdx.y>>4, h=blockIdx.y&15;
    const int q0=blockIdx.x*128;
    const unsigned* Qg=g_qkv + ((size_t)(b*NHEAD+h))*SEQ*HDIM;
    const unsigned* Kg=Qg + QKOFF;
    const unsigned* Vg=Kg + QKOFF;
    unsigned* Pw = Ps + warp*2048;

    // lane-transpose permutations for the P fragment buffer
    const int sigL = ((lane&3)<<3) + (lane>>2);          // load-side
    const int l1   = (g<<2) + ((2*tg)&3);                // producer lane 1 (even)
    const int sig1 = (((l1  )&3)<<3) + (l1>>2);
    const int sig2 = (((l1+1)&3)<<3) + (l1>>2);          // (l1+1)>>2 == l1>>2
    const int sOff = 2*(tg>>1);

    #pragma unroll
    for(int i=0;i<16;i++){
        int idx=tid+(i<<7);
        int r=idx>>4, c=(idx&15)<<2;
        *(uint4*)&Qs[r*FSTR+c] = *(const uint4*)(Qg+(size_t)(q0+r)*HDIM+c);
    }

    float oc[2][8][4];
    #pragma unroll
    for(int mi=0;mi<2;mi++)
        #pragma unroll
        for(int i=0;i<8;i++)
            #pragma unroll
            for(int j=0;j<4;j++) oc[mi][i][j]=0.f;
    float mrow[4], lrow[4];
    #pragma unroll
    for(int i=0;i<4;i++){ mrow[i]=-1e30f; lrow[i]=0.f; }
    const float scale=0.125f*1.44269504089f;

    for(int kt=0;kt<SEQ/64;kt++){
        __syncthreads();
        #pragma unroll
        for(int i=0;i<8;i++){
            int idx=tid+(i<<7);
            int r=idx>>4, c=(idx&15)<<2;
            *(uint4*)&Ks[r*FSTR+c] = *(const uint4*)(Kg+(size_t)(kt*64+r)*HDIM+c);
            *(uint4*)&Vs[r*FSTR+c] = *(const uint4*)(Vg+(size_t)(kt*64+r)*HDIM+c);
        }
        __syncthreads();

        // S = Q @ K^T : 2 m-tiles x 8 key-tiles
        float sc[2][8][4];
        #pragma unroll
        for(int mi=0;mi<2;mi++)
            #pragma unroll
            for(int i=0;i<8;i++)
                #pragma unroll
                for(int j=0;j<4;j++) sc[mi][i][j]=0.f;
        #pragma unroll
        for(int ks=0;ks<8;ks++){
            const int k0=ks*8;
            unsigned af[2][4];
            #pragma unroll
            for(int mi=0;mi<2;mi++){
                const int m0=qb+mi*16;
                af[mi][0]=Qs[(m0+g  )*FSTR+k0+tg];
                af[mi][1]=Qs[(m0+g+8)*FSTR+k0+tg];
                af[mi][2]=Qs[(m0+g  )*FSTR+k0+tg+4];
                af[mi][3]=Qs[(m0+g+8)*FSTR+k0+tg+4];
            }
            #pragma unroll
            for(int ni=0;ni<8;ni++){
                unsigned bf[2];
                bf[0]=Ks[(ni*8+g)*FSTR+k0+tg];
                bf[1]=Ks[(ni*8+g)*FSTR+k0+tg+4];
                mma8(sc[0][ni],af[0],bf);
                mma8(sc[1][ni],af[1],bf);
            }
        }

        // online softmax per m-tile
        float al[4];
        #pragma unroll
        for(int mi=0;mi<2;mi++){
            float mx0=-1e30f, mx1=-1e30f;
            #pragma unroll
            for(int ni=0;ni<8;ni++){
                sc[mi][ni][0]*=scale; sc[mi][ni][1]*=scale;
                sc[mi][ni][2]*=scale; sc[mi][ni][3]*=scale;
                mx0=fmaxf(mx0,fmaxf(sc[mi][ni][0],sc[mi][ni][1]));
                mx1=fmaxf(mx1,fmaxf(sc[mi][ni][2],sc[mi][ni][3]));
            }
            mx0=fmaxf(mx0,__shfl_xor_sync(0xffffffffu,mx0,1));
            mx0=fmaxf(mx0,__shfl_xor_sync(0xffffffffu,mx0,2));
            mx1=fmaxf(mx1,__shfl_xor_sync(0xffffffffu,mx1,1));
            mx1=fmaxf(mx1,__shfl_xor_sync(0xffffffffu,mx1,2));
            const float nm0=fmaxf(mrow[mi*2],mx0), nm1=fmaxf(mrow[mi*2+1],mx1);
            al[mi*2]  =exp2f(mrow[mi*2]-nm0);
            al[mi*2+1]=exp2f(mrow[mi*2+1]-nm1);
            mrow[mi*2]=nm0; mrow[mi*2+1]=nm1;
            float s0=0.f, s1=0.f;
            #pragma unroll
            for(int ni=0;ni<8;ni++){
                sc[mi][ni][0]=exp2f(sc[mi][ni][0]-nm0);
                sc[mi][ni][1]=exp2f(sc[mi][ni][1]-nm0);
                sc[mi][ni][2]=exp2f(sc[mi][ni][2]-nm1);
                sc[mi][ni][3]=exp2f(sc[mi][ni][3]-nm1);
                s0+=sc[mi][ni][0]+sc[mi][ni][1];
                s1+=sc[mi][ni][2]+sc[mi][ni][3];
            }
            s0+=__shfl_xor_sync(0xffffffffu,s0,1); s0+=__shfl_xor_sync(0xffffffffu,s0,2);
            s1+=__shfl_xor_sync(0xffffffffu,s1,1); s1+=__shfl_xor_sync(0xffffffffu,s1,2);
            lrow[mi*2]  =lrow[mi*2]  *al[mi*2]  +s0;
            lrow[mi*2+1]=lrow[mi*2+1]*al[mi*2+1]+s1;
        }

        // P -> per-warp fragment buffers, lane-transposed addressing
        #pragma unroll
        for(int mi=0;mi<2;mi++){
            unsigned* Pm = Pw + mi*1024;
            #pragma unroll
            for(int ni=0;ni<8;ni++){
                *(uint2*)&Pm[ni*128 + sig1*4 + sOff]=
                    make_uint2(f2tf(sc[mi][ni][0]), f2tf(sc[mi][ni][2]));
                *(uint2*)&Pm[ni*128 + sig2*4 + sOff]=
                    make_uint2(f2tf(sc[mi][ni][1]), f2tf(sc[mi][ni][3]));
            }
        }
        __syncwarp();

        #pragma unroll
        for(int mi=0;mi<2;mi++)
            #pragma unroll
            for(int di=0;di<8;di++){
                oc[mi][di][0]*=al[mi*2];   oc[mi][di][1]*=al[mi*2];
                oc[mi][di][2]*=al[mi*2+1]; oc[mi][di][3]*=al[mi*2+1];
            }
        // O += P @ V
        #pragma unroll
        for(int ks=0;ks<8;ks++){
            const int k0=ks*8;
            uint4 af4[2];
            af4[0]=*(const uint4*)&Pw[        ks*128 + sigL*4];
            af4[1]=*(const uint4*)&Pw[1024 +  ks*128 + sigL*4];
            #pragma unroll
            for(int di=0;di<8;di++){
                unsigned bf[2];
                bf[0]=Vs[(k0+tg  )*FSTR+di*8+g];
                bf[1]=Vs[(k0+tg+4)*FSTR+di*8+g];
                mma8(oc[0][di],(const unsigned*)&af4[0],bf);
                mma8(oc[1][di],(const unsigned*)&af4[1],bf);
            }
        }
        __syncwarp();
    }

    #pragma unroll
    for(int mi=0;mi<2;mi++){
        const float i0=1.f/lrow[mi*2], i1=1.f/lrow[mi*2+1];
        const int r0=q0+qb+mi*16+g, r1=r0+8;
        unsigned* O0=&g_attn[((size_t)(b*SEQ)+r0)*DIMC + h*HDIM];
        unsigned* O1=&g_attn[((size_t)(b*SEQ)+r1)*DIMC + h*HDIM];
        #pragma unroll
        for(int di=0;di<8;di++){
            const int c=di*8+2*tg;
            *(uint2*)&O0[c]=make_uint2(f2tf(oc[mi][di][0]*i0), f2tf(oc[mi][di][1]*i0));
            *(uint2*)&O1[c]=make_uint2(f2tf(oc[mi][di][2]*i1), f2tf(oc[mi][di][3]*i1));
        }
    }
}

// ---------------------------------------------------------------------------
extern "C" void kernel_launch(void* const* d_in, const int* in_sizes, int n_in,
                              void* d_out, int out_size)
{
    const float* x     = (const float*)d_in[0];
    const float* Wqkv  = (const float*)d_in[1];
    const float* bqkv  = (const float*)d_in[2];
    const float* Wproj = (const float*)d_in[3];
    const float* bproj = (const float*)d_in[4];
    float* out = (float*)d_out;

    cudaFuncSetAttribute(flash_mma, cudaFuncAttributeMaxDynamicSharedMemorySize, FLASH_SMEM);

    unsigned *xtf, *wqkv, *wprj;
    cudaGetSymbolAddress((void**)&xtf,  g_xtf);
    cudaGetSymbolAddress((void**)&wqkv, g_wqkv);
    cudaGetSymbolAddress((void**)&wprj, g_wprj);

    cvt_tf32<<<(MTOT*DIMC/4+255)/256, 256>>>((const float4*)x,     (uint4*)xtf,  MTOT*DIMC/4);
    cvt_tf32<<<(DIMC*NQKV/4+255)/256, 256>>>((const float4*)Wqkv,  (uint4*)wqkv, DIMC*NQKV/4);
    cvt_tf32<<<(DIMC*DIMC/4+255)/256, 256>>>((const float4*)Wproj, (uint4*)wprj, DIMC*DIMC/4);

    dim3 g1(NQKV/128, MTOT/128);   // (24, 64)
    gemm_mma<NQKV, true><<<g1, 128>>>(xtf, wqkv, bqkv, nullptr);

    dim3 g2(SEQ/128, BATCH*NHEAD); // (16, 64)
    flash_mma<<<g2, 128, FLASH_SMEM>>>();

    dim3 g3(DIMC/128, MTOT/128);   // (8, 64)
    gemm_mma<DIMC, false><<<g3, 128>>>(nullptr, wprj, bproj, out);
}

// round 12
// speedup vs baseline: 1.0964x; 1.0964x over previous
#include <cuda_runtime.h>

#define DIMC 1024
#define NHEAD 16
#define HDIM 64
#define BATCH 4
#define SEQ 2048
#define MTOT (BATCH*SEQ)
#define NQKV (3*DIMC)

// All intermediates hold TF32 bit patterns
__device__ unsigned g_xtf [(size_t)MTOT*DIMC];
__device__ unsigned g_wqkv[(size_t)DIMC*NQKV];
__device__ unsigned g_wprj[(size_t)DIMC*DIMC];
__device__ unsigned g_qkv [(size_t)3*BATCH*NHEAD*SEQ*HDIM];  // [3][B][H][S][D]
__device__ unsigned g_attn[(size_t)MTOT*DIMC];               // [B*S][C] tf32

__device__ __forceinline__ unsigned f2tf(float x){
    unsigned r; asm("cvt.rna.tf32.f32 %0,%1;" : "=r"(r) : "f"(x)); return r;
}

__device__ __forceinline__ void mma8(float* c, const unsigned* a, const unsigned* b){
    asm volatile(
      "mma.sync.aligned.m16n8k8.row.col.f32.tf32.tf32.f32 "
      "{%0,%1,%2,%3},{%4,%5,%6,%7},{%8,%9},{%0,%1,%2,%3};\n"
      : "+f"(c[0]),"+f"(c[1]),"+f"(c[2]),"+f"(c[3])
      : "r"(a[0]),"r"(a[1]),"r"(a[2]),"r"(a[3]),"r"(b[0]),"r"(b[1]));
}

__global__ __launch_bounds__(256)
void cvt_tf32(const float4* __restrict__ src, uint4* __restrict__ dst, int n4)
{
    int i = blockIdx.x*256 + threadIdx.x;
    if(i < n4){
        float4 v = src[i];
        dst[i] = make_uint4(f2tf(v.x), f2tf(v.y), f2tf(v.z), f2tf(v.w));
    }
}

// ---------------------------------------------------------------------------
// Tensor-core GEMM (R11 version — proven): 64x64 warp tiles, 128 threads,
// A smem XOR-swizzled m' = m ^ ((k&12)<<1).
// ---------------------------------------------------------------------------
#define ASTR 136
#define BSTR 136

template<int N, bool SCATTER>
__global__ __launch_bounds__(128)
void gemm_mma(const unsigned* __restrict__ A, const unsigned* __restrict__ B,
              const float* __restrict__ bias, float* __restrict__ out)
{
    __shared__ __align__(16) unsigned As[2][16*ASTR];
    __shared__ __align__(16) unsigned Bs[2][16*BSTR];
    const int tid=threadIdx.x, lane=tid&31, warp=tid>>5;
    const int g=lane>>2, tg=lane&3;
    const int mbase=(warp&1)*64, nbase=(warp>>1)*64;
    const int bm=blockIdx.y*128, bn=blockIdx.x*128;
    const unsigned* Ab = (SCATTER ? A : (const unsigned*)g_attn) + (size_t)bm*DIMC;
    const unsigned* Bb = B + bn;

    uint4 ar[4], br[4];
    float acc[4][8][4];
    #pragma unroll
    for(int i=0;i<4;i++)
      #pragma unroll
      for(int j=0;j<8;j++)
        #pragma unroll
        for(int k=0;k<4;k++) acc[i][j][k]=0.f;

    const int NT = DIMC/16;

    #pragma unroll
    for(int i=0;i<4;i++){
        int idx=tid+(i<<7);
        ar[i]=*(const uint4*)(Ab + (size_t)(idx>>2)*DIMC + ((idx&3)<<2));
        br[i]=*(const uint4*)(Bb + (size_t)(idx>>5)*N + ((idx&31)<<2));
    }
    #pragma unroll
    for(int i=0;i<4;i++){
        int idx=tid+(i<<7);
        int r=idx>>2, kc=(idx&3)<<2;
        int rs = r ^ (kc<<1);
        As[0][(kc+0)*ASTR+rs]=ar[i].x;
        As[0][(kc+1)*ASTR+rs]=ar[i].y;
        As[0][(kc+2)*ASTR+rs]=ar[i].z;
        As[0][(kc+3)*ASTR+rs]=ar[i].w;
        int rb=idx>>5, cb=(idx&31)<<2;
        *(uint4*)&Bs[0][rb*BSTR+cb]=br[i];
    }
    __syncthreads();

    for(int kt=0;kt<NT;kt++){
        const int buf=kt&1;
        if(kt<NT-1){
            #pragma unroll
            for(int i=0;i<4;i++){
                int idx=tid+(i<<7);
                ar[i]=*(const uint4*)(Ab + (size_t)(idx>>2)*DIMC + (kt+1)*16 + ((idx&3)<<2));
                br[i]=*(const uint4*)(Bb + (size_t)((kt+1)*16+(idx>>5))*N + ((idx&31)<<2));
            }
        }
        #pragma unroll
        for(int ks=0;ks<2;ks++){
            const int k0=ks*8;
            const int sw01 = (k0&12)<<1;
            const int sw23 = ((k0+4)&12)<<1;
            unsigned af[4][4], bf[8][2];
            #pragma unroll
            for(int mi=0;mi<4;mi++){
                const int m0=mbase+mi*16;
                af[mi][0]=As[buf][(k0+tg  )*ASTR+((m0+g  )^sw01)];
                af[mi][1]=As[buf][(k0+tg  )*ASTR+((m0+g+8)^sw01)];
                af[mi][2]=As[buf][(k0+tg+4)*ASTR+((m0+g  )^sw23)];
                af[mi][3]=As[buf][(k0+tg+4)*ASTR+((m0+g+8)^sw23)];
            }
            #pragma unroll
            for(int ni=0;ni<8;ni++){
                const int n0=nbase+ni*8;
                bf[ni][0]=Bs[buf][(k0+tg)*BSTR+n0+g];
                bf[ni][1]=Bs[buf][(k0+tg+4)*BSTR+n0+g];
            }
            #pragma unroll
            for(int mi=0;mi<4;mi++)
                #pragma unroll
                for(int ni=0;ni<8;ni++)
                    mma8(acc[mi][ni],af[mi],bf[ni]);
        }
        if(kt<NT-1){
            #pragma unroll
            for(int i=0;i<4;i++){
                int idx=tid+(i<<7);
                int r=idx>>2, kc=(idx&3)<<2;
                int rs = r ^ (kc<<1);
                As[buf^1][(kc+0)*ASTR+rs]=ar[i].x;
                As[buf^1][(kc+1)*ASTR+rs]=ar[i].y;
                As[buf^1][(kc+2)*ASTR+rs]=ar[i].z;
                As[buf^1][(kc+3)*ASTR+rs]=ar[i].w;
                int rb=idx>>5, cb=(idx&31)<<2;
                *(uint4*)&Bs[buf^1][rb*BSTR+cb]=br[i];
            }
        }
        __syncthreads();
    }

    #pragma unroll
    for(int mi=0;mi<4;mi++){
        #pragma unroll
        for(int ni=0;ni<8;ni++){
            #pragma unroll
            for(int e=0;e<4;e++){
                const int r = bm + mbase + mi*16 + g + ((e>=2)?8:0);
                const int c = bn + nbase + ni*8 + 2*tg + (e&1);
                const float v = acc[mi][ni][e] + bias[c];
                if(SCATTER){
                    const int b=r>>11, s=r&2047;
                    const int t=c>>10, h=(c>>6)&15, d=c&63;
                    g_qkv[((((size_t)t*BATCH+b)*NHEAD+h)*SEQ+s)*HDIM+d]=f2tf(v);
                } else {
                    out[(size_t)r*N+c]=v;
                }
            }
        }
    }
}

// ---------------------------------------------------------------------------
// Flash attention (R10 body): 128 threads, 4 warps x 32 q-rows, q-tile 128.
// P buffer now 128B-XOR-swizzled: phys = logical ^ (((logical>>5)&3)<<2)
// -> conflict-free on BOTH store (uint2) and load (uint4) sides.
// ---------------------------------------------------------------------------
#define QKOFF ((size_t)BATCH*NHEAD*SEQ*HDIM)
#define FSTR 68
#define FLASH_SMEM ((128*FSTR + 2*64*FSTR + 4*2048)*4)   /* 102400 B */

__global__ __launch_bounds__(128)
void flash_mma()
{
    extern __shared__ __align__(16) unsigned sm[];
    unsigned* Qs=sm;
    unsigned* Ks=Qs+128*FSTR;
    unsigned* Vs=Ks+64*FSTR;
    unsigned* Ps=Vs+64*FSTR;
    const int tid=threadIdx.x, lane=tid&31, warp=tid>>5;
    const int g=lane>>2, tg=lane&3;
    const int qb=warp*32;
    const int b=blockIdx.y>>4, h=blockIdx.y&15;
    const int q0=blockIdx.x*128;
    const unsigned* Qg=g_qkv + ((size_t)(b*NHEAD+h))*SEQ*HDIM;
    const unsigned* Kg=Qg + QKOFF;
    const unsigned* Vg=Kg + QKOFF;
    unsigned* Pw = Ps + warp*2048;

    // P-buffer swizzled per-thread offsets (masks are ks/ni-invariant)
    const int pbase = (g*4 + ((2*tg)&3))*4 + 2*(tg>>1);  // R10 logical store base
    const int pmS   = ((g>>1)&3)<<2;
    const int ps1   = pbase ^ pmS;
    const int ps2   = (pbase+4) ^ pmS;
    const int plL   = (lane*4) ^ (((lane>>3)&3)<<2);     // load side

    #pragma unroll
    for(int i=0;i<16;i++){
        int idx=tid+(i<<7);
        int r=idx>>4, c=(idx&15)<<2;
        *(uint4*)&Qs[r*FSTR+c] = *(const uint4*)(Qg+(size_t)(q0+r)*HDIM+c);
    }

    float oc[2][8][4];
    #pragma unroll
    for(int mi=0;mi<2;mi++)
        #pragma unroll
        for(int i=0;i<8;i++)
            #pragma unroll
            for(int j=0;j<4;j++) oc[mi][i][j]=0.f;
    float mrow[4], lrow[4];
    #pragma unroll
    for(int i=0;i<4;i++){ mrow[i]=-1e30f; lrow[i]=0.f; }
    const float scale=0.125f*1.44269504089f;

    for(int kt=0;kt<SEQ/64;kt++){
        __syncthreads();
        #pragma unroll
        for(int i=0;i<8;i++){
            int idx=tid+(i<<7);
            int r=idx>>4, c=(idx&15)<<2;
            *(uint4*)&Ks[r*FSTR+c] = *(const uint4*)(Kg+(size_t)(kt*64+r)*HDIM+c);
            *(uint4*)&Vs[r*FSTR+c] = *(const uint4*)(Vg+(size_t)(kt*64+r)*HDIM+c);
        }
        __syncthreads();

        // S = Q @ K^T : 2 m-tiles x 8 key-tiles
        float sc[2][8][4];
        #pragma unroll
        for(int mi=0;mi<2;mi++)
            #pragma unroll
            for(int i=0;i<8;i++)
                #pragma unroll
                for(int j=0;j<4;j++) sc[mi][i][j]=0.f;
        #pragma unroll
        for(int ks=0;ks<8;ks++){
            const int k0=ks*8;
            unsigned af[2][4];
            #pragma unroll
            for(int mi=0;mi<2;mi++){
                const int m0=qb+mi*16;
                af[mi][0]=Qs[(m0+g  )*FSTR+k0+tg];
                af[mi][1]=Qs[(m0+g+8)*FSTR+k0+tg];
                af[mi][2]=Qs[(m0+g  )*FSTR+k0+tg+4];
                af[mi][3]=Qs[(m0+g+8)*FSTR+k0+tg+4];
            }
            #pragma unroll
            for(int ni=0;ni<8;ni++){
                unsigned bf[2];
                bf[0]=Ks[(ni*8+g)*FSTR+k0+tg];
                bf[1]=Ks[(ni*8+g)*FSTR+k0+tg+4];
                mma8(sc[0][ni],af[0],bf);
                mma8(sc[1][ni],af[1],bf);
            }
        }

        // online softmax per m-tile
        float al[4];
        #pragma unroll
        for(int mi=0;mi<2;mi++){
            float mx0=-1e30f, mx1=-1e30f;
            #pragma unroll
            for(int ni=0;ni<8;ni++){
                sc[mi][ni][0]*=scale; sc[mi][ni][1]*=scale;
                sc[mi][ni][2]*=scale; sc[mi][ni][3]*=scale;
                mx0=fmaxf(mx0,fmaxf(sc[mi][ni][0],sc[mi][ni][1]));
                mx1=fmaxf(mx1,fmaxf(sc[mi][ni][2],sc[mi][ni][3]));
            }
            mx0=fmaxf(mx0,__shfl_xor_sync(0xffffffffu,mx0,1));
            mx0=fmaxf(mx0,__shfl_xor_sync(0xffffffffu,mx0,2));
            mx1=fmaxf(mx1,__shfl_xor_sync(0xffffffffu,mx1,1));
            mx1=fmaxf(mx1,__shfl_xor_sync(0xffffffffu,mx1,2));
            const float nm0=fmaxf(mrow[mi*2],mx0), nm1=fmaxf(mrow[mi*2+1],mx1);
            al[mi*2]  =exp2f(mrow[mi*2]-nm0);
            al[mi*2+1]=exp2f(mrow[mi*2+1]-nm1);
            mrow[mi*2]=nm0; mrow[mi*2+1]=nm1;
            float s0=0.f, s1=0.f;
            #pragma unroll
            for(int ni=0;ni<8;ni++){
                sc[mi][ni][0]=exp2f(sc[mi][ni][0]-nm0);
                sc[mi][ni][1]=exp2f(sc[mi][ni][1]-nm0);
                sc[mi][ni][2]=exp2f(sc[mi][ni][2]-nm1);
                sc[mi][ni][3]=exp2f(sc[mi][ni][3]-nm1);
                s0+=sc[mi][ni][0]+sc[mi][ni][1];
                s1+=sc[mi][ni][2]+sc[mi][ni][3];
            }
            s0+=__shfl_xor_sync(0xffffffffu,s0,1); s0+=__shfl_xor_sync(0xffffffffu,s0,2);
            s1+=__shfl_xor_sync(0xffffffffu,s1,1); s1+=__shfl_xor_sync(0xffffffffu,s1,2);
            lrow[mi*2]  =lrow[mi*2]  *al[mi*2]  +s0;
            lrow[mi*2+1]=lrow[mi*2+1]*al[mi*2+1]+s1;
        }

        // P -> per-warp fragment buffers (XOR-swizzled, conflict-free)
        #pragma unroll
        for(int mi=0;mi<2;mi++){
            unsigned* Pm = Pw + mi*1024;
            #pragma unroll
            for(int ni=0;ni<8;ni++){
                *(uint2*)&Pm[ni*128 + ps1]=
                    make_uint2(f2tf(sc[mi][ni][0]), f2tf(sc[mi][ni][2]));
                *(uint2*)&Pm[ni*128 + ps2]=
                    make_uint2(f2tf(sc[mi][ni][1]), f2tf(sc[mi][ni][3]));
            }
        }
        __syncwarp();

        #pragma unroll
        for(int mi=0;mi<2;mi++)
            #pragma unroll
            for(int di=0;di<8;di++){
                oc[mi][di][0]*=al[mi*2];   oc[mi][di][1]*=al[mi*2];
                oc[mi][di][2]*=al[mi*2+1]; oc[mi][di][3]*=al[mi*2+1];
            }
        // O += P @ V
        #pragma unroll
        for(int ks=0;ks<8;ks++){
            const int k0=ks*8;
            uint4 af4[2];
            af4[0]=*(const uint4*)&Pw[        ks*128 + plL];
            af4[1]=*(const uint4*)&Pw[1024 +  ks*128 + plL];
            #pragma unroll
            for(int di=0;di<8;di++){
                unsigned bf[2];
                bf[0]=Vs[(k0+tg  )*FSTR+di*8+g];
                bf[1]=Vs[(k0+tg+4)*FSTR+di*8+g];
                mma8(oc[0][di],(const unsigned*)&af4[0],bf);
                mma8(oc[1][di],(const unsigned*)&af4[1],bf);
            }
        }
        __syncwarp();
    }

    #pragma unroll
    for(int mi=0;mi<2;mi++){
        const float i0=1.f/lrow[mi*2], i1=1.f/lrow[mi*2+1];
        const int r0=q0+qb+mi*16+g, r1=r0+8;
        unsigned* O0=&g_attn[((size_t)(b*SEQ)+r0)*DIMC + h*HDIM];
        unsigned* O1=&g_attn[((size_t)(b*SEQ)+r1)*DIMC + h*HDIM];
        #pragma unroll
        for(int di=0;di<8;di++){
            const int c=di*8+2*tg;
            *(uint2*)&O0[c]=make_uint2(f2tf(oc[mi][di][0]*i0), f2tf(oc[mi][di][1]*i0));
            *(uint2*)&O1[c]=make_uint2(f2tf(oc[mi][di][2]*i1), f2tf(oc[mi][di][3]*i1));
        }
    }
}

// ---------------------------------------------------------------------------
extern "C" void kernel_launch(void* const* d_in, const int* in_sizes, int n_in,
                              void* d_out, int out_size)
{
    const float* x     = (const float*)d_in[0];
    const float* Wqkv  = (const float*)d_in[1];
    const float* bqkv  = (const float*)d_in[2];
    const float* Wproj = (const float*)d_in[3];
    const float* bproj = (const float*)d_in[4];
    float* out = (float*)d_out;

    cudaFuncSetAttribute(flash_mma, cudaFuncAttributeMaxDynamicSharedMemorySize, FLASH_SMEM);

    unsigned *xtf, *wqkv, *wprj;
    cudaGetSymbolAddress((void**)&xtf,  g_xtf);
    cudaGetSymbolAddress((void**)&wqkv, g_wqkv);
    cudaGetSymbolAddress((void**)&wprj, g_wprj);

    cvt_tf32<<<(MTOT*DIMC/4+255)/256, 256>>>((const float4*)x,     (uint4*)xtf,  MTOT*DIMC/4);
    cvt_tf32<<<(DIMC*NQKV/4+255)/256, 256>>>((const float4*)Wqkv,  (uint4*)wqkv, DIMC*NQKV/4);
    cvt_tf32<<<(DIMC*DIMC/4+255)/256, 256>>>((const float4*)Wproj, (uint4*)wprj, DIMC*DIMC/4);

    dim3 g1(NQKV/128, MTOT/128);   // (24, 64)
    gemm_mma<NQKV, true><<<g1, 128>>>(xtf, wqkv, bqkv, nullptr);

    dim3 g2(SEQ/128, BATCH*NHEAD); // (16, 64)
    flash_mma<<<g2, 128, FLASH_SMEM>>>();

    dim3 g3(DIMC/128, MTOT/128);   // (8, 64)
    gemm_mma<DIMC, false><<<g3, 128>>>(nullptr, wprj, bproj, out);
}

// round 13
// speedup vs baseline: 1.1676x; 1.0649x over previous
#include <cuda_runtime.h>
#include <cstdint>

#define DIMC 1024
#define NHEAD 16
#define HDIM 64
#define BATCH 4
#define SEQ 2048
#define MTOT (BATCH*SEQ)
#define NQKV (3*DIMC)

// All intermediates hold TF32 bit patterns
__device__ unsigned g_xtf [(size_t)MTOT*DIMC];
__device__ unsigned g_wqkv[(size_t)DIMC*NQKV];
__device__ unsigned g_wprj[(size_t)DIMC*DIMC];
__device__ unsigned g_qkv [(size_t)3*BATCH*NHEAD*SEQ*HDIM];  // [3][B][H][S][D]
__device__ unsigned g_attn[(size_t)MTOT*DIMC];               // [B*S][C] tf32

__device__ __forceinline__ unsigned f2tf(float x){
    unsigned r; asm("cvt.rna.tf32.f32 %0,%1;" : "=r"(r) : "f"(x)); return r;
}

__device__ __forceinline__ void mma8(float* c, const unsigned* a, const unsigned* b){
    asm volatile(
      "mma.sync.aligned.m16n8k8.row.col.f32.tf32.tf32.f32 "
      "{%0,%1,%2,%3},{%4,%5,%6,%7},{%8,%9},{%0,%1,%2,%3};\n"
      : "+f"(c[0]),"+f"(c[1]),"+f"(c[2]),"+f"(c[3])
      : "r"(a[0]),"r"(a[1]),"r"(a[2]),"r"(a[3]),"r"(b[0]),"r"(b[1]));
}

__device__ __forceinline__ uint32_t smem_u32(const void* p){
    uint32_t a;
    asm("{ .reg .u64 t; cvta.to.shared.u64 t, %1; cvt.u32.u64 %0, t; }":"=r"(a):"l"(p));
    return a;
}
__device__ __forceinline__ void cpa16(uint32_t dst, const void* src){
    asm volatile("cp.async.cg.shared.global [%0], [%1], 16;" :: "r"(dst), "l"(src));
}
#define CPA_COMMIT() asm volatile("cp.async.commit_group;" ::: "memory")

// Fused fp32 -> tf32 conversion for all three inputs
#define XN4   (MTOT*DIMC/4)       /* 2097152 */
#define WQN4  (DIMC*NQKV/4)       /*  786432 */
#define WPN4  (DIMC*DIMC/4)       /*  262144 */
__global__ __launch_bounds__(256)
void cvt_all(const float4* __restrict__ x, const float4* __restrict__ wq,
             const float4* __restrict__ wp)
{
    int i = blockIdx.x*256 + threadIdx.x;
    const float4* s; uint4* d; int off;
    if(i < XN4){ s=x; d=(uint4*)g_xtf; off=i; }
    else if(i < XN4+WQN4){ s=wq; d=(uint4*)g_wqkv; off=i-XN4; }
    else if(i < XN4+WQN4+WPN4){ s=wp; d=(uint4*)g_wprj; off=i-XN4-WQN4; }
    else return;
    float4 v = s[off];
    d[off] = make_uint4(f2tf(v.x), f2tf(v.y), f2tf(v.z), f2tf(v.w));
}

// ---------------------------------------------------------------------------
// Tensor-core GEMM (R11/R12 proven): 64x64 warp tiles, 128 threads,
// A smem XOR-swizzled m' = m ^ ((k&12)<<1).
// ---------------------------------------------------------------------------
#define ASTR 136
#define BSTR 136

template<int N, bool SCATTER>
__global__ __launch_bounds__(128)
void gemm_mma(const unsigned* __restrict__ A, const unsigned* __restrict__ B,
              const float* __restrict__ bias, float* __restrict__ out)
{
    __shared__ __align__(16) unsigned As[2][16*ASTR];
    __shared__ __align__(16) unsigned Bs[2][16*BSTR];
    const int tid=threadIdx.x, lane=tid&31, warp=tid>>5;
    const int g=lane>>2, tg=lane&3;
    const int mbase=(warp&1)*64, nbase=(warp>>1)*64;
    const int bm=blockIdx.y*128, bn=blockIdx.x*128;
    const unsigned* Ab = (SCATTER ? A : (const unsigned*)g_attn) + (size_t)bm*DIMC;
    const unsigned* Bb = B + bn;

    uint4 ar[4], br[4];
    float acc[4][8][4];
    #pragma unroll
    for(int i=0;i<4;i++)
      #pragma unroll
      for(int j=0;j<8;j++)
        #pragma unroll
        for(int k=0;k<4;k++) acc[i][j][k]=0.f;

    const int NT = DIMC/16;

    #pragma unroll
    for(int i=0;i<4;i++){
        int idx=tid+(i<<7);
        ar[i]=*(const uint4*)(Ab + (size_t)(idx>>2)*DIMC + ((idx&3)<<2));
        br[i]=*(const uint4*)(Bb + (size_t)(idx>>5)*N + ((idx&31)<<2));
    }
    #pragma unroll
    for(int i=0;i<4;i++){
        int idx=tid+(i<<7);
        int r=idx>>2, kc=(idx&3)<<2;
        int rs = r ^ (kc<<1);
        As[0][(kc+0)*ASTR+rs]=ar[i].x;
        As[0][(kc+1)*ASTR+rs]=ar[i].y;
        As[0][(kc+2)*ASTR+rs]=ar[i].z;
        As[0][(kc+3)*ASTR+rs]=ar[i].w;
        int rb=idx>>5, cb=(idx&31)<<2;
        *(uint4*)&Bs[0][rb*BSTR+cb]=br[i];
    }
    __syncthreads();

    for(int kt=0;kt<NT;kt++){
        const int buf=kt&1;
        if(kt<NT-1){
            #pragma unroll
            for(int i=0;i<4;i++){
                int idx=tid+(i<<7);
                ar[i]=*(const uint4*)(Ab + (size_t)(idx>>2)*DIMC + (kt+1)*16 + ((idx&3)<<2));
                br[i]=*(const uint4*)(Bb + (size_t)((kt+1)*16+(idx>>5))*N + ((idx&31)<<2));
            }
        }
        #pragma unroll
        for(int ks=0;ks<2;ks++){
            const int k0=ks*8;
            const int sw01 = (k0&12)<<1;
            const int sw23 = ((k0+4)&12)<<1;
            unsigned af[4][4], bf[8][2];
            #pragma unroll
            for(int mi=0;mi<4;mi++){
                const int m0=mbase+mi*16;
                af[mi][0]=As[buf][(k0+tg  )*ASTR+((m0+g  )^sw01)];
                af[mi][1]=As[buf][(k0+tg  )*ASTR+((m0+g+8)^sw01)];
                af[mi][2]=As[buf][(k0+tg+4)*ASTR+((m0+g  )^sw23)];
                af[mi][3]=As[buf][(k0+tg+4)*ASTR+((m0+g+8)^sw23)];
            }
            #pragma unroll
            for(int ni=0;ni<8;ni++){
                const int n0=nbase+ni*8;
                bf[ni][0]=Bs[buf][(k0+tg)*BSTR+n0+g];
                bf[ni][1]=Bs[buf][(k0+tg+4)*BSTR+n0+g];
            }
            #pragma unroll
            for(int mi=0;mi<4;mi++)
                #pragma unroll
                for(int ni=0;ni<8;ni++)
                    mma8(acc[mi][ni],af[mi],bf[ni]);
        }
        if(kt<NT-1){
            #pragma unroll
            for(int i=0;i<4;i++){
                int idx=tid+(i<<7);
                int r=idx>>2, kc=(idx&3)<<2;
                int rs = r ^ (kc<<1);
                As[buf^1][(kc+0)*ASTR+rs]=ar[i].x;
                As[buf^1][(kc+1)*ASTR+rs]=ar[i].y;
                As[buf^1][(kc+2)*ASTR+rs]=ar[i].z;
                As[buf^1][(kc+3)*ASTR+rs]=ar[i].w;
                int rb=idx>>5, cb=(idx&31)<<2;
                *(uint4*)&Bs[buf^1][rb*BSTR+cb]=br[i];
            }
        }
        __syncthreads();
    }

    #pragma unroll
    for(int mi=0;mi<4;mi++){
        #pragma unroll
        for(int ni=0;ni<8;ni++){
            #pragma unroll
            for(int e=0;e<4;e++){
                const int r = bm + mbase + mi*16 + g + ((e>=2)?8:0);
                const int c = bn + nbase + ni*8 + 2*tg + (e&1);
                const float v = acc[mi][ni][e] + bias[c];
                if(SCATTER){
                    const int b=r>>11, s=r&2047;
                    const int t=c>>10, h=(c>>6)&15, d=c&63;
                    g_qkv[((((size_t)t*BATCH+b)*NHEAD+h)*SEQ+s)*HDIM+d]=f2tf(v);
                } else {
                    out[(size_t)r*N+c]=v;
                }
            }
        }
    }
}

// ---------------------------------------------------------------------------
// Flash attention: 128 threads, 4 warps x 32 q-rows, q-tile 128, k-tile 64.
// Q fragments in REGISTERS (scale folded in), K/V double-buffered cp.async.
// P buffer 128B-XOR-swizzled (R12-proven).
// ---------------------------------------------------------------------------
#define QKOFF ((size_t)BATCH*NHEAD*SEQ*HDIM)
#define FSTR 68
#define KVBUF (2*64*FSTR)                       /* one K+V buffer pair, words */
#define FLASH_SMEM ((2*KVBUF + 8*1024)*4)       /* 102400 B -> 2 CTAs/SM */

__global__ __launch_bounds__(128)
void flash_mma()
{
    extern __shared__ __align__(16) unsigned sm[];
    unsigned* Ps = sm + 2*KVBUF;                // 8192 words (also Q staging)
    const int tid=threadIdx.x, lane=tid&31, warp=tid>>5;
    const int g=lane>>2, tg=lane&3;
    const int qb=warp*32;
    const int b=blockIdx.y>>4, h=blockIdx.y&15;
    const int q0=blockIdx.x*128;
    const unsigned* Qg=g_qkv + ((size_t)(b*NHEAD+h))*SEQ*HDIM;
    const unsigned* Kg=Qg + QKOFF;
    const unsigned* Vg=Kg + QKOFF;
    unsigned* Pw = Ps + warp*2048;
    const uint32_t smb = smem_u32(sm);

    // P-buffer swizzled offsets (R12-proven)
    const int pbase = (g*4 + ((2*tg)&3))*4 + 2*(tg>>1);
    const int pmS   = ((g>>1)&3)<<2;
    const int ps1   = pbase ^ pmS;
    const int ps2   = (pbase+4) ^ pmS;
    const int plL   = (lane*4) ^ (((lane>>3)&3)<<2);

    // Prologue: issue cp.async for K/V tiles 0 and 1
    #pragma unroll
    for(int t=0;t<2;t++){
        const uint32_t kb = smb + t*KVBUF*4;
        #pragma unroll
        for(int i=0;i<8;i++){
            int idx=tid+(i<<7);
            int r=idx>>4, c=(idx&15)<<2;
            cpa16(kb + (r*FSTR+c)*4,            Kg+(size_t)(t*64+r)*HDIM+c);
            cpa16(kb + (64*FSTR + r*FSTR+c)*4,  Vg+(size_t)(t*64+r)*HDIM+c);
        }
        CPA_COMMIT();
    }

    // Stage Q tile into P region ([r][c] stride 64), then hoist to registers
    #pragma unroll
    for(int i=0;i<16;i++){
        int idx=tid+(i<<7);
        int r=idx>>4, c=(idx&15)<<2;
        *(uint4*)&Ps[r*64+c] = *(const uint4*)(Qg+(size_t)(q0+r)*HDIM+c);
    }
    __syncthreads();
    const float qs = 0.125f*1.44269504089f;     // scale*log2e folded into Q
    unsigned qf[8][2][4];
    #pragma unroll
    for(int ks=0;ks<8;ks++){
        const int k0=ks*8;
        #pragma unroll
        for(int mi=0;mi<2;mi++){
            const int m0=qb+mi*16;
            qf[ks][mi][0]=f2tf(__uint_as_float(Ps[(m0+g  )*64+k0+tg  ])*qs);
            qf[ks][mi][1]=f2tf(__uint_as_float(Ps[(m0+g+8)*64+k0+tg  ])*qs);
            qf[ks][mi][2]=f2tf(__uint_as_float(Ps[(m0+g  )*64+k0+tg+4])*qs);
            qf[ks][mi][3]=f2tf(__uint_as_float(Ps[(m0+g+8)*64+k0+tg+4])*qs);
        }
    }
    __syncthreads();   // staging reads done before P region reused

    float oc[2][8][4];
    #pragma unroll
    for(int mi=0;mi<2;mi++)
        #pragma unroll
        for(int i=0;i<8;i++)
            #pragma unroll
            for(int j=0;j<4;j++) oc[mi][i][j]=0.f;
    float mrow[4], lrow[4];
    #pragma unroll
    for(int i=0;i<4;i++){ mrow[i]=-1e30f; lrow[i]=0.f; }

    const int NKT = SEQ/64;
    for(int kt=0;kt<NKT;kt++){
        if(kt<NKT-1){ asm volatile("cp.async.wait_group 1;" ::: "memory"); }
        else        { asm volatile("cp.async.wait_group 0;" ::: "memory"); }
        __syncthreads();
        const unsigned* Kb = sm + (kt&1)*KVBUF;
        const unsigned* Vb = Kb + 64*FSTR;

        // S = Q @ K^T
        float sc[2][8][4];
        #pragma unroll
        for(int mi=0;mi<2;mi++)
            #pragma unroll
            for(int i=0;i<8;i++)
                #pragma unroll
                for(int j=0;j<4;j++) sc[mi][i][j]=0.f;
        #pragma unroll
        for(int ks=0;ks<8;ks++){
            const int k0=ks*8;
            #pragma unroll
            for(int ni=0;ni<8;ni++){
                unsigned bf[2];
                bf[0]=Kb[(ni*8+g)*FSTR+k0+tg];
                bf[1]=Kb[(ni*8+g)*FSTR+k0+tg+4];
                mma8(sc[0][ni],qf[ks][0],bf);
                mma8(sc[1][ni],qf[ks][1],bf);
            }
        }

        // online softmax (scale already folded into Q)
        float al[4];
        #pragma unroll
        for(int mi=0;mi<2;mi++){
            float mx0=-1e30f, mx1=-1e30f;
            #pragma unroll
            for(int ni=0;ni<8;ni++){
                mx0=fmaxf(mx0,fmaxf(sc[mi][ni][0],sc[mi][ni][1]));
                mx1=fmaxf(mx1,fmaxf(sc[mi][ni][2],sc[mi][ni][3]));
            }
            mx0=fmaxf(mx0,__shfl_xor_sync(0xffffffffu,mx0,1));
            mx0=fmaxf(mx0,__shfl_xor_sync(0xffffffffu,mx0,2));
            mx1=fmaxf(mx1,__shfl_xor_sync(0xffffffffu,mx1,1));
            mx1=fmaxf(mx1,__shfl_xor_sync(0xffffffffu,mx1,2));
            const float nm0=fmaxf(mrow[mi*2],mx0), nm1=fmaxf(mrow[mi*2+1],mx1);
            al[mi*2]  =exp2f(mrow[mi*2]-nm0);
            al[mi*2+1]=exp2f(mrow[mi*2+1]-nm1);
            mrow[mi*2]=nm0; mrow[mi*2+1]=nm1;
            float s0=0.f, s1=0.f;
            #pragma unroll
            for(int ni=0;ni<8;ni++){
                sc[mi][ni][0]=exp2f(sc[mi][ni][0]-nm0);
                sc[mi][ni][1]=exp2f(sc[mi][ni][1]-nm0);
                sc[mi][ni][2]=exp2f(sc[mi][ni][2]-nm1);
                sc[mi][ni][3]=exp2f(sc[mi][ni][3]-nm1);
                s0+=sc[mi][ni][0]+sc[mi][ni][1];
                s1+=sc[mi][ni][2]+sc[mi][ni][3];
            }
            s0+=__shfl_xor_sync(0xffffffffu,s0,1); s0+=__shfl_xor_sync(0xffffffffu,s0,2);
            s1+=__shfl_xor_sync(0xffffffffu,s1,1); s1+=__shfl_xor_sync(0xffffffffu,s1,2);
            lrow[mi*2]  =lrow[mi*2]  *al[mi*2]  +s0;
            lrow[mi*2+1]=lrow[mi*2+1]*al[mi*2+1]+s1;
        }

        // P -> per-warp fragment buffers (XOR-swizzled)
        #pragma unroll
        for(int mi=0;mi<2;mi++){
            unsigned* Pm = Pw + mi*1024;
            #pragma unroll
            for(int ni=0;ni<8;ni++){
                *(uint2*)&Pm[ni*128 + ps1]=
                    make_uint2(f2tf(sc[mi][ni][0]), f2tf(sc[mi][ni][2]));
                *(uint2*)&Pm[ni*128 + ps2]=
                    make_uint2(f2tf(sc[mi][ni][1]), f2tf(sc[mi][ni][3]));
            }
        }
        __syncwarp();

        #pragma unroll
        for(int mi=0;mi<2;mi++)
            #pragma unroll
            for(int di=0;di<8;di++){
                oc[mi][di][0]*=al[mi*2];   oc[mi][di][1]*=al[mi*2];
                oc[mi][di][2]*=al[mi*2+1]; oc[mi][di][3]*=al[mi*2+1];
            }
        // O += P @ V
        #pragma unroll
        for(int ks=0;ks<8;ks++){
            const int k0=ks*8;
            uint4 af4[2];
            af4[0]=*(const uint4*)&Pw[        ks*128 + plL];
            af4[1]=*(const uint4*)&Pw[1024 +  ks*128 + plL];
            #pragma unroll
            for(int di=0;di<8;di++){
                unsigned bf[2];
                bf[0]=Vb[(k0+tg  )*FSTR+di*8+g];
                bf[1]=Vb[(k0+tg+4)*FSTR+di*8+g];
                mma8(oc[0][di],(const unsigned*)&af4[0],bf);
                mma8(oc[1][di],(const unsigned*)&af4[1],bf);
            }
        }
        __syncthreads();   // all warps done reading this K/V buffer
        if(kt<NKT-2){
            const uint32_t kb = smb + (kt&1)*KVBUF*4;
            #pragma unroll
            for(int i=0;i<8;i++){
                int idx=tid+(i<<7);
                int r=idx>>4, c=(idx&15)<<2;
                cpa16(kb + (r*FSTR+c)*4,           Kg+(size_t)((kt+2)*64+r)*HDIM+c);
                cpa16(kb + (64*FSTR + r*FSTR+c)*4, Vg+(size_t)((kt+2)*64+r)*HDIM+c);
            }
            CPA_COMMIT();
        }
    }

    #pragma unroll
    for(int mi=0;mi<2;mi++){
        const float i0=1.f/lrow[mi*2], i1=1.f/lrow[mi*2+1];
        const int r0=q0+qb+mi*16+g, r1=r0+8;
        unsigned* O0=&g_attn[((size_t)(b*SEQ)+r0)*DIMC + h*HDIM];
        unsigned* O1=&g_attn[((size_t)(b*SEQ)+r1)*DIMC + h*HDIM];
        #pragma unroll
        for(int di=0;di<8;di++){
            const int c=di*8+2*tg;
            *(uint2*)&O0[c]=make_uint2(f2tf(oc[mi][di][0]*i0), f2tf(oc[mi][di][1]*i0));
            *(uint2*)&O1[c]=make_uint2(f2tf(oc[mi][di][2]*i1), f2tf(oc[mi][di][3]*i1));
        }
    }
}

// ---------------------------------------------------------------------------
extern "C" void kernel_launch(void* const* d_in, const int* in_sizes, int n_in,
                              void* d_out, int out_size)
{
    const float* x     = (const float*)d_in[0];
    const float* Wqkv  = (const float*)d_in[1];
    const float* bqkv  = (const float*)d_in[2];
    const float* Wproj = (const float*)d_in[3];
    const float* bproj = (const float*)d_in[4];
    float* out = (float*)d_out;

    cudaFuncSetAttribute(flash_mma, cudaFuncAttributeMaxDynamicSharedMemorySize, FLASH_SMEM);

    unsigned *xtf, *wqkv, *wprj;
    cudaGetSymbolAddress((void**)&xtf,  g_xtf);
    cudaGetSymbolAddress((void**)&wqkv, g_wqkv);
    cudaGetSymbolAddress((void**)&wprj, g_wprj);

    cvt_all<<<(XN4+WQN4+WPN4+255)/256, 256>>>((const float4*)x, (const float4*)Wqkv,
                                              (const float4*)Wproj);

    dim3 g1(NQKV/128, MTOT/128);   // (24, 64)
    gemm_mma<NQKV, true><<<g1, 128>>>(xtf, wqkv, bqkv, nullptr);

    dim3 g2(SEQ/128, BATCH*NHEAD); // (16, 64)
    flash_mma<<<g2, 128, FLASH_SMEM>>>();

    dim3 g3(DIMC/128, MTOT/128);   // (8, 64)
    gemm_mma<DIMC, false><<<g3, 128>>>(nullptr, wprj, bproj, out);
}

// round 14
// speedup vs baseline: 2.3457x; 2.0091x over previous
#include <cuda_runtime.h>
#include <cuda_fp16.h>
#include <cstdint>

#define DIMC 1024
#define DIMW 512                 /* packed half2 words per row */
#define NHEAD 16
#define HDIM 64
#define HDW 32                   /* packed words per head row */
#define BATCH 4
#define SEQ 2048
#define MTOT (BATCH*SEQ)
#define NQKV (3*DIMC)

// Packed half2 storage (word = (even k, odd k))
__device__ unsigned g_xtf [(size_t)MTOT*DIMW];
__device__ unsigned g_wqkv[(size_t)DIMW*NQKV];   // [kpair][n]
__device__ unsigned g_wprj[(size_t)DIMW*DIMC];   // [kpair][n]
__device__ unsigned g_qkv [(size_t)3*BATCH*NHEAD*SEQ*HDW];  // [3][B][H][S][dpair]
__device__ unsigned g_attn[(size_t)MTOT*DIMW];

__device__ __forceinline__ unsigned packh2(float a, float b){
    __half2 h = __floats2half2_rn(a,b);
    return *(unsigned*)&h;
}
__device__ __forceinline__ float2 uph2(unsigned u){
    __half2 h = *(__half2*)&u;
    return __half22float2(h);
}
__device__ __forceinline__ void mma16(float* c, const unsigned* a, const unsigned* b){
    asm volatile(
      "mma.sync.aligned.m16n8k16.row.col.f32.f16.f16.f32 "
      "{%0,%1,%2,%3},{%4,%5,%6,%7},{%8,%9},{%0,%1,%2,%3};\n"
      : "+f"(c[0]),"+f"(c[1]),"+f"(c[2]),"+f"(c[3])
      : "r"(a[0]),"r"(a[1]),"r"(a[2]),"r"(a[3]),"r"(b[0]),"r"(b[1]));
}
__device__ __forceinline__ uint32_t smem_u32(const void* p){
    uint32_t a;
    asm("{ .reg .u64 t; cvta.to.shared.u64 t, %1; cvt.u32.u64 %0, t; }":"=r"(a):"l"(p));
    return a;
}
__device__ __forceinline__ void cpa16(uint32_t dst, const void* src){
    asm volatile("cp.async.cg.shared.global [%0], [%1], 16;" :: "r"(dst), "l"(src));
}
#define CPA_COMMIT() asm volatile("cp.async.commit_group;" ::: "memory")
__device__ __forceinline__ void ldmx4t(unsigned* r, uint32_t addr){
    asm volatile("ldmatrix.sync.aligned.m8n8.x4.trans.shared.b16 {%0,%1,%2,%3}, [%4];"
        : "=r"(r[0]),"=r"(r[1]),"=r"(r[2]),"=r"(r[3]) : "r"(addr));
}

// ---------------------------------------------------------------------------
// Conversion kernels: fp32 -> packed half2
// ---------------------------------------------------------------------------
__global__ __launch_bounds__(256)
void cvt_x(const float4* __restrict__ src, uint2* __restrict__ dst, int n4)
{
    int i = blockIdx.x*256 + threadIdx.x;
    if(i < n4){
        float4 v = src[i];
        dst[i] = make_uint2(packh2(v.x,v.y), packh2(v.z,v.w));
    }
}
// W [K][N] row-major -> [K/2][N] words (word = (W[2k'][n], W[2k'+1][n]))
__global__ __launch_bounds__(256)
void cvt_w(const float* __restrict__ src, unsigned* __restrict__ dst, int N, int tot)
{
    int i = blockIdx.x*256 + threadIdx.x;
    if(i < tot){
        int kp = i / N, n = i - kp*N;
        dst[i] = packh2(src[(size_t)(2*kp)*N+n], src[(size_t)(2*kp+1)*N+n]);
    }
}

// ---------------------------------------------------------------------------
// fp16 tensor-core GEMM (R13 skeleton, k reinterpreted as k-pairs):
// 64x64 warp tiles, 128 threads, block 128x128, kt covers 32 k (16 kpairs).
// ---------------------------------------------------------------------------
#define ASTR 136
#define BSTR 136

template<int N, bool SCATTER>
__global__ __launch_bounds__(128)
void gemm_mma(const unsigned* __restrict__ A, const unsigned* __restrict__ B,
              const float* __restrict__ bias, float* __restrict__ out)
{
    __shared__ __align__(16) unsigned As[2][16*ASTR];
    __shared__ __align__(16) unsigned Bs[2][16*BSTR];
    const int tid=threadIdx.x, lane=tid&31, warp=tid>>5;
    const int g=lane>>2, tg=lane&3;
    const int mbase=(warp&1)*64, nbase=(warp>>1)*64;
    const int bm=blockIdx.y*128, bn=blockIdx.x*128;
    const unsigned* Ab = (SCATTER ? A : (const unsigned*)g_attn) + (size_t)bm*DIMW;
    const unsigned* Bb = B + bn;

    uint4 ar[4], br[4];
    float acc[4][8][4];
    #pragma unroll
    for(int i=0;i<4;i++)
      #pragma unroll
      for(int j=0;j<8;j++)
        #pragma unroll
        for(int k=0;k<4;k++) acc[i][j][k]=0.f;

    const int NT = DIMW/16;   // 32 kts of 16 kpairs

    #pragma unroll
    for(int i=0;i<4;i++){
        int idx=tid+(i<<7);
        ar[i]=*(const uint4*)(Ab + (size_t)(idx>>2)*DIMW + ((idx&3)<<2));
        br[i]=*(const uint4*)(Bb + (size_t)(idx>>5)*N + ((idx&31)<<2));
    }
    #pragma unroll
    for(int i=0;i<4;i++){
        int idx=tid+(i<<7);
        int r=idx>>2, kc=(idx&3)<<2;
        int rs = r ^ (kc<<1);
        As[0][(kc+0)*ASTR+rs]=ar[i].x;
        As[0][(kc+1)*ASTR+rs]=ar[i].y;
        As[0][(kc+2)*ASTR+rs]=ar[i].z;
        As[0][(kc+3)*ASTR+rs]=ar[i].w;
        int rb=idx>>5, cb=(idx&31)<<2;
        *(uint4*)&Bs[0][rb*BSTR+cb]=br[i];
    }
    __syncthreads();

    for(int kt=0;kt<NT;kt++){
        const int buf=kt&1;
        if(kt<NT-1){
            #pragma unroll
            for(int i=0;i<4;i++){
                int idx=tid+(i<<7);
                ar[i]=*(const uint4*)(Ab + (size_t)(idx>>2)*DIMW + (kt+1)*16 + ((idx&3)<<2));
                br[i]=*(const uint4*)(Bb + (size_t)((kt+1)*16+(idx>>5))*N + ((idx&31)<<2));
            }
        }
        #pragma unroll
        for(int ks=0;ks<2;ks++){
            const int k0=ks*8;
            const int sw01 = (k0&12)<<1;
            const int sw23 = ((k0+4)&12)<<1;
            unsigned af[4][4], bf[8][2];
            #pragma unroll
            for(int mi=0;mi<4;mi++){
                const int m0=mbase+mi*16;
                af[mi][0]=As[buf][(k0+tg  )*ASTR+((m0+g  )^sw01)];
                af[mi][1]=As[buf][(k0+tg  )*ASTR+((m0+g+8)^sw01)];
                af[mi][2]=As[buf][(k0+tg+4)*ASTR+((m0+g  )^sw23)];
                af[mi][3]=As[buf][(k0+tg+4)*ASTR+((m0+g+8)^sw23)];
            }
            #pragma unroll
            for(int ni=0;ni<8;ni++){
                const int n0=nbase+ni*8;
                bf[ni][0]=Bs[buf][(k0+tg)*BSTR+n0+g];
                bf[ni][1]=Bs[buf][(k0+tg+4)*BSTR+n0+g];
            }
            #pragma unroll
            for(int mi=0;mi<4;mi++)
                #pragma unroll
                for(int ni=0;ni<8;ni++)
                    mma16(acc[mi][ni],af[mi],bf[ni]);
        }
        if(kt<NT-1){
            #pragma unroll
            for(int i=0;i<4;i++){
                int idx=tid+(i<<7);
                int r=idx>>2, kc=(idx&3)<<2;
                int rs = r ^ (kc<<1);
                As[buf^1][(kc+0)*ASTR+rs]=ar[i].x;
                As[buf^1][(kc+1)*ASTR+rs]=ar[i].y;
                As[buf^1][(kc+2)*ASTR+rs]=ar[i].z;
                As[buf^1][(kc+3)*ASTR+rs]=ar[i].w;
                int rb=idx>>5, cb=(idx&31)<<2;
                *(uint4*)&Bs[buf^1][rb*BSTR+cb]=br[i];
            }
        }
        __syncthreads();
    }

    #pragma unroll
    for(int mi=0;mi<4;mi++){
        #pragma unroll
        for(int ni=0;ni<8;ni++){
            #pragma unroll
            for(int e2=0;e2<2;e2++){
                const int r = bm + mbase + mi*16 + g + (e2?8:0);
                const int c = bn + nbase + ni*8 + 2*tg;
                const float v0 = acc[mi][ni][e2*2+0] + bias[c];
                const float v1 = acc[mi][ni][e2*2+1] + bias[c+1];
                if(SCATTER){
                    const int b=r>>11, s=r&2047;
                    const int t=c>>10, h=(c>>6)&15, dp=(c&63)>>1;
                    g_qkv[((((size_t)t*BATCH+b)*NHEAD+h)*SEQ+s)*HDW+dp]=packh2(v0,v1);
                } else {
                    *(float2*)&out[(size_t)r*N+c]=make_float2(v0,v1);
                }
            }
        }
    }
}

// ---------------------------------------------------------------------------
// fp16 flash attention: 128 thr, 4 warps x 32 q-rows, q-tile 128, k-tile 64.
// Q frags in regs (scale folded); P stays in registers (C-frag == A-frag);
// V frags via ldmatrix.x4.trans; K/V double-buffered cp.async.
// Smem layouts [row][dpair] stride 36 (conflict-free everywhere).
// ---------------------------------------------------------------------------
#define QKOFF ((size_t)BATCH*NHEAD*SEQ*HDW)
#define KVST 36
#define KVW (2*64*KVST)                        /* K+V pair, words = 4608 */
#define QSTG (128*KVST)                        /* 4608 words */
#define FLASH_SMEM ((2*KVW + QSTG)*4)          /* 55296 B */

__global__ __launch_bounds__(128)
void flash_mma()
{
    extern __shared__ __align__(16) unsigned sm[];
    unsigned* Qst = sm + 2*KVW;
    const int tid=threadIdx.x, lane=tid&31, warp=tid>>5;
    const int g=lane>>2, tg=lane&3;
    const int qb=warp*32;
    const int b=blockIdx.y>>4, h=blockIdx.y&15;
    const int q0=blockIdx.x*128;
    const unsigned* Qg=g_qkv + ((size_t)(b*NHEAD+h))*SEQ*HDW;
    const unsigned* Kg=Qg + QKOFF;
    const unsigned* Vg=Kg + QKOFF;
    const uint32_t smb = smem_u32(sm);

    // ldmatrix per-lane constant offset: mat = lane>>3
    const int mat = lane>>3;
    const int ldmOff = (((mat&1)*8 + (lane&7))*KVST + (mat>>1)*4)*4;  // bytes

    // Prologue: cp.async K/V tiles 0,1
    #pragma unroll
    for(int t=0;t<2;t++){
        const uint32_t kb = smb + t*KVW*4;
        #pragma unroll
        for(int i=0;i<4;i++){
            int idx=tid+(i<<7);
            int r=idx>>3, c4=(idx&7)<<2;
            cpa16(kb + (r*KVST+c4)*4,              Kg+(size_t)(t*64+r)*HDW+c4);
            cpa16(kb + ((64+r)*KVST+c4)*4,         Vg+(size_t)(t*64+r)*HDW+c4);
        }
        CPA_COMMIT();
    }

    // Stage Q (packed words) then hoist scaled fp16 fragments to registers
    #pragma unroll
    for(int i=0;i<8;i++){
        int idx=tid+(i<<7);
        int r=idx>>3, c4=(idx&7)<<2;
        *(uint4*)&Qst[r*KVST+c4] = *(const uint4*)(Qg+(size_t)(q0+r)*HDW+c4);
    }
    __syncthreads();
    const float qs = 0.125f*1.44269504089f;
    unsigned qf[4][2][4];
    #pragma unroll
    for(int kg=0;kg<4;kg++){
        #pragma unroll
        for(int mi=0;mi<2;mi++){
            const int m0=qb+mi*16;
            #pragma unroll
            for(int s=0;s<4;s++){
                const int row = m0 + g + ((s&1)?8:0);
                const int dp  = kg*8 + tg + ((s>=2)?4:0);
                float2 v = uph2(Qst[row*KVST+dp]);
                qf[kg][mi][s] = packh2(v.x*qs, v.y*qs);
            }
        }
    }
    __syncthreads();

    float oc[2][8][4];
    #pragma unroll
    for(int mi=0;mi<2;mi++)
        #pragma unroll
        for(int i=0;i<8;i++)
            #pragma unroll
            for(int j=0;j<4;j++) oc[mi][i][j]=0.f;
    float mrow[4], lrow[4];
    #pragma unroll
    for(int i=0;i<4;i++){ mrow[i]=-1e30f; lrow[i]=0.f; }

    const int NKT = SEQ/64;
    for(int kt=0;kt<NKT;kt++){
        if(kt<NKT-1){ asm volatile("cp.async.wait_group 1;" ::: "memory"); }
        else        { asm volatile("cp.async.wait_group 0;" ::: "memory"); }
        __syncthreads();
        const unsigned* Kb = sm + (kt&1)*KVW;
        const uint32_t vbase = smb + ((kt&1)*KVW + 64*KVST)*4;

        // S = Q @ K^T  (4 kgroups of d16, 8 key-tiles, 2 mi)
        float sc[2][8][4];
        #pragma unroll
        for(int mi=0;mi<2;mi++)
            #pragma unroll
            for(int i=0;i<8;i++)
                #pragma unroll
                for(int j=0;j<4;j++) sc[mi][i][j]=0.f;
        #pragma unroll
        for(int kg=0;kg<4;kg++){
            #pragma unroll
            for(int ni=0;ni<8;ni++){
                unsigned bf[2];
                bf[0]=Kb[(ni*8+g)*KVST + kg*8+tg];
                bf[1]=Kb[(ni*8+g)*KVST + kg*8+tg+4];
                mma16(sc[0][ni],qf[kg][0],bf);
                mma16(sc[1][ni],qf[kg][1],bf);
            }
        }

        // online softmax + pack P to fp16 register fragments
        float al[4];
        unsigned pk[2][8][2];
        #pragma unroll
        for(int mi=0;mi<2;mi++){
            float mx0=-1e30f, mx1=-1e30f;
            #pragma unroll
            for(int ni=0;ni<8;ni++){
                mx0=fmaxf(mx0,fmaxf(sc[mi][ni][0],sc[mi][ni][1]));
                mx1=fmaxf(mx1,fmaxf(sc[mi][ni][2],sc[mi][ni][3]));
            }
            mx0=fmaxf(mx0,__shfl_xor_sync(0xffffffffu,mx0,1));
            mx0=fmaxf(mx0,__shfl_xor_sync(0xffffffffu,mx0,2));
            mx1=fmaxf(mx1,__shfl_xor_sync(0xffffffffu,mx1,1));
            mx1=fmaxf(mx1,__shfl_xor_sync(0xffffffffu,mx1,2));
            const float nm0=fmaxf(mrow[mi*2],mx0), nm1=fmaxf(mrow[mi*2+1],mx1);
            al[mi*2]  =exp2f(mrow[mi*2]-nm0);
            al[mi*2+1]=exp2f(mrow[mi*2+1]-nm1);
            mrow[mi*2]=nm0; mrow[mi*2+1]=nm1;
            float s0=0.f, s1=0.f;
            #pragma unroll
            for(int ni=0;ni<8;ni++){
                float e0=exp2f(sc[mi][ni][0]-nm0);
                float e1=exp2f(sc[mi][ni][1]-nm0);
                float e2=exp2f(sc[mi][ni][2]-nm1);
                float e3=exp2f(sc[mi][ni][3]-nm1);
                s0+=e0+e1; s1+=e2+e3;
                pk[mi][ni][0]=packh2(e0,e1);
                pk[mi][ni][1]=packh2(e2,e3);
            }
            s0+=__shfl_xor_sync(0xffffffffu,s0,1); s0+=__shfl_xor_sync(0xffffffffu,s0,2);
            s1+=__shfl_xor_sync(0xffffffffu,s1,1); s1+=__shfl_xor_sync(0xffffffffu,s1,2);
            lrow[mi*2]  =lrow[mi*2]  *al[mi*2]  +s0;
            lrow[mi*2+1]=lrow[mi*2+1]*al[mi*2+1]+s1;
        }

        #pragma unroll
        for(int mi=0;mi<2;mi++)
            #pragma unroll
            for(int di=0;di<8;di++){
                oc[mi][di][0]*=al[mi*2];   oc[mi][di][1]*=al[mi*2];
                oc[mi][di][2]*=al[mi*2+1]; oc[mi][di][3]*=al[mi*2+1];
            }

        // O += P @ V : P from registers, V via ldmatrix.x4.trans
        #pragma unroll
        for(int kg=0;kg<4;kg++){
            unsigned ap[2][4];
            #pragma unroll
            for(int mi=0;mi<2;mi++){
                ap[mi][0]=pk[mi][2*kg  ][0];
                ap[mi][1]=pk[mi][2*kg  ][1];
                ap[mi][2]=pk[mi][2*kg+1][0];
                ap[mi][3]=pk[mi][2*kg+1][1];
            }
            #pragma unroll
            for(int dd=0;dd<4;dd++){
                unsigned vr[4];
                ldmx4t(vr, vbase + ldmOff + (kg*16*KVST + dd*8)*4);
                mma16(oc[0][2*dd  ],ap[0],vr);
                mma16(oc[0][2*dd+1],ap[0],vr+2);
                mma16(oc[1][2*dd  ],ap[1],vr);
                mma16(oc[1][2*dd+1],ap[1],vr+2);
            }
        }
        __syncthreads();
        if(kt<NKT-2){
            const uint32_t kb = smb + (kt&1)*KVW*4;
            #pragma unroll
            for(int i=0;i<4;i++){
                int idx=tid+(i<<7);
                int r=idx>>3, c4=(idx&7)<<2;
                cpa16(kb + (r*KVST+c4)*4,      Kg+(size_t)((kt+2)*64+r)*HDW+c4);
                cpa16(kb + ((64+r)*KVST+c4)*4, Vg+(size_t)((kt+2)*64+r)*HDW+c4);
            }
            CPA_COMMIT();
        }
    }

    // Epilogue: normalize, pack, write g_attn
    #pragma unroll
    for(int mi=0;mi<2;mi++){
        const float i0=1.f/lrow[mi*2], i1=1.f/lrow[mi*2+1];
        const int r0=q0+qb+mi*16+g, r1=r0+8;
        unsigned* O0=&g_attn[(size_t)(b*SEQ+r0)*DIMW + h*HDW];
        unsigned* O1=&g_attn[(size_t)(b*SEQ+r1)*DIMW + h*HDW];
        #pragma unroll
        for(int di=0;di<8;di++){
            O0[di*4+tg]=packh2(oc[mi][di][0]*i0, oc[mi][di][1]*i0);
            O1[di*4+tg]=packh2(oc[mi][di][2]*i1, oc[mi][di][3]*i1);
        }
    }
}

// ---------------------------------------------------------------------------
extern "C" void kernel_launch(void* const* d_in, const int* in_sizes, int n_in,
                              void* d_out, int out_size)
{
    const float* x     = (const float*)d_in[0];
    const float* Wqkv  = (const float*)d_in[1];
    const float* bqkv  = (const float*)d_in[2];
    const float* Wproj = (const float*)d_in[3];
    const float* bproj = (const float*)d_in[4];
    float* out = (float*)d_out;

    cudaFuncSetAttribute(flash_mma, cudaFuncAttributeMaxDynamicSharedMemorySize, FLASH_SMEM);

    unsigned *xtf, *wqkv, *wprj;
    cudaGetSymbolAddress((void**)&xtf,  g_xtf);
    cudaGetSymbolAddress((void**)&wqkv, g_wqkv);
    cudaGetSymbolAddress((void**)&wprj, g_wprj);

    cvt_x<<<(MTOT*DIMC/4+255)/256, 256>>>((const float4*)x, (uint2*)xtf, MTOT*DIMC/4);
    cvt_w<<<(DIMW*NQKV+255)/256, 256>>>(Wqkv, wqkv, NQKV, DIMW*NQKV);
    cvt_w<<<(DIMW*DIMC+255)/256, 256>>>(Wproj, wprj, DIMC, DIMW*DIMC);

    dim3 g1(NQKV/128, MTOT/128);   // (24, 64)
    gemm_mma<NQKV, true><<<g1, 128>>>(xtf, wqkv, bqkv, nullptr);

    dim3 g2(SEQ/128, BATCH*NHEAD); // (16, 64)
    flash_mma<<<g2, 128, FLASH_SMEM>>>();

    dim3 g3(DIMC/128, MTOT/128);   // (8, 64)
    gemm_mma<DIMC, false><<<g3, 128>>>(nullptr, wprj, bproj, out);
}